// round 16
// baseline (speedup 1.0000x reference)
#include <cuda_runtime.h>
#include <cuda_bf16.h>

// GCN: out = log_softmax( GCN2( relu(GCN1(x)) ) ), Agg = D^-1/2 (A+I) D^-1/2.
//
// Algebraic restructurings:
//  (1) Linearity: aggregation commutes with the dense right-multiply, so both
//      layers aggregate 2-wide features (layer 2 down-projects BEFORE scatter).
//  (2) Normalization split: out[d] = dinv[d]*( sum_{s->d} (dinv[s]*f[s]) +
//      dinv[d]*f[d] ) -> edge kernel does NO dinv loads.
//
// R16: int32 fast path. Evidence (R9 crash under an int64 interpretation)
// says the harness delivers edge_index as int32. In that case the edge
// kernels read the src/dst rows DIRECTLY (coalesced int4), and the pre-pass
// only counts degrees from the dst row (12.8MB) — no g_edge materialization.
// The int64 fallback (detected per-block from odd 32-bit words; false-positive
// probability ~1e-40 on random int32) converts into g_edge as before.
//
// Pipeline (6 kernels, graph-capturable, allocation-free):
//   K1 deg (int32: dst-row only; int64: convert to g_edge too); publishes flag
//   K2 node1: dinv, xs = dinv*x, seed agg = xs, restore deg=0
//   K3 edge1: agg[d] += xs[s]
//   K4 node_mid: t=relu((dinv*agg)@W1+b1)@W2; ts=dinv*t; seed agg=ts
//   K5 edge2: agg[d] += ts[s]
//   K6 out = log_softmax(dinv*agg + b2)

#define MAXN 100352    // N_NODES = 100000, padded
#define MAXE 3276800   // E = 3200000, padded

__device__ int      g_idx64;         // published by k_deg block 0
__device__ unsigned g_deg[MAXN];     // zero at load; self-restored each call
__device__ float    g_dinv[MAXN];
__device__ float2   g_xs[MAXN];
__device__ float2   g_t[MAXN];
__device__ float2   g_agg[MAXN];
__device__ int2     g_edge[MAXE];    // used only on the int64 fallback path

__device__ __forceinline__ void red_add_v2(float2* addr, float a, float b) {
    // sm_90+ vector float reduction, fire-and-forget (no L2 return trip)
    asm volatile("red.global.add.v2.f32 [%0], {%1, %2};"
                 :: "l"(addr), "f"(a), "f"(b) : "memory");
}

__device__ __forceinline__ void red_add_u32(unsigned* addr, unsigned v) {
    asm volatile("red.global.add.u32 [%0], %1;" :: "l"(addr), "r"(v) : "memory");
}

// Degree pass, 4 edges/thread. Per-block dtype detect; int32: read dst row
// only; int64: convert both rows into g_edge (fallback). Block 0 publishes
// the flag for the edge kernels.
__global__ void k_deg(const void* __restrict__ ei, long long E) {
    __shared__ int s_idx64;
    long long i = (long long)blockIdx.x * blockDim.x + threadIdx.x;
    long long e = 4 * i;

    if (threadIdx.x == 0) {
        // Sample 8 odd 32-bit words of this block's chunk of the src row:
        // int64 values < 2^31 have all-zero high halves.
        long long base = 4 * (long long)blockIdx.x * blockDim.x;
        const int* w = (const int*)ei;
        int all_zero = 1;
        #pragma unroll
        for (int k = 0; k < 8; k++) {
            long long pos = 2 * (base + k) + 1;
            if (pos < 2 * E && w[pos] != 0) { all_zero = 0; break; }
        }
        s_idx64 = all_zero;
        if (blockIdx.x == 0) g_idx64 = all_zero;
    }
    __syncthreads();
    int idx64 = s_idx64;

    if (!idx64) {
        // Fast path: degrees from the dst row only (coalesced int4).
        const int* dst = (const int*)ei + E;
        if (e + 3 < E) {
            int4 d4 = __ldcs(reinterpret_cast<const int4*>(dst) + i);
            red_add_u32(&g_deg[d4.x], 1u);
            red_add_u32(&g_deg[d4.y], 1u);
            red_add_u32(&g_deg[d4.z], 1u);
            red_add_u32(&g_deg[d4.w], 1u);
        } else {
            for (long long k = e; k < E; k++) red_add_u32(&g_deg[dst[k]], 1u);
        }
    } else {
        // Fallback: convert int64 -> packed int2 g_edge + degrees.
        if (e + 3 < E) {
            const ulonglong2* ps = (const ulonglong2*)ei;
            const ulonglong2* pd = (const ulonglong2*)((const long long*)ei + E);
            ulonglong2 s01 = __ldcs(ps + 2 * i);
            ulonglong2 s23 = __ldcs(ps + 2 * i + 1);
            ulonglong2 d01 = __ldcs(pd + 2 * i);
            ulonglong2 d23 = __ldcs(pd + 2 * i + 1);
            int4 r0 = make_int4((int)s01.x, (int)d01.x, (int)s01.y, (int)d01.y);
            int4 r1 = make_int4((int)s23.x, (int)d23.x, (int)s23.y, (int)d23.y);
            reinterpret_cast<int4*>(g_edge)[2 * i]     = r0;
            reinterpret_cast<int4*>(g_edge)[2 * i + 1] = r1;
            red_add_u32(&g_deg[r0.y], 1u);
            red_add_u32(&g_deg[r0.w], 1u);
            red_add_u32(&g_deg[r1.y], 1u);
            red_add_u32(&g_deg[r1.w], 1u);
        } else {
            const long long* p = (const long long*)ei;
            for (long long k = e; k < E; k++) {
                int s0 = (int)p[k], d0 = (int)p[E + k];
                g_edge[k] = make_int2(s0, d0);
                red_add_u32(&g_deg[d0], 1u);
            }
        }
    }
}

// dinv = rsqrt(indeg+1); xs = dinv*x; seed agg = xs; RESTORE deg=0 so the
// zero-at-entry invariant holds for the next call/replay (no zero pass).
__global__ void k_node1(const float2* __restrict__ x, int n) {
    int v = blockIdx.x * blockDim.x + threadIdx.x;
    if (v < n) {
        float dv = rsqrtf((float)(g_deg[v] + 1u));
        g_deg[v] = 0u;
        g_dinv[v] = dv;
        float2 xv = x[v];
        float2 s = make_float2(xv.x * dv, xv.y * dv);
        g_xs[v] = s;
        g_agg[v] = s;
    }
}

// Minimal edge scatter: agg[dst] += feat[src]. 4 edges/thread.
// int32: index straight from the input rows (int4, coalesced);
// int64 fallback: packed g_edge. Uniform branch on g_idx64.
template <bool USE_T>
__global__ void k_edge(const int* __restrict__ ei32, long long E) {
    const float2* feat = USE_T ? g_t : g_xs;
    long long i = (long long)blockIdx.x * blockDim.x + threadIdx.x;
    long long e = 4 * i;
    if (!g_idx64) {
        const int* dst = ei32 + E;
        if (e + 3 < E) {
            int4 s4 = __ldcs(reinterpret_cast<const int4*>(ei32) + i);
            int4 d4 = __ldcs(reinterpret_cast<const int4*>(dst) + i);
            float2 f0 = __ldg(&feat[s4.x]);
            float2 f1 = __ldg(&feat[s4.y]);
            float2 f2 = __ldg(&feat[s4.z]);
            float2 f3 = __ldg(&feat[s4.w]);
            red_add_v2(&g_agg[d4.x], f0.x, f0.y);
            red_add_v2(&g_agg[d4.y], f1.x, f1.y);
            red_add_v2(&g_agg[d4.z], f2.x, f2.y);
            red_add_v2(&g_agg[d4.w], f3.x, f3.y);
        } else {
            for (long long k = e; k < E; k++) {
                float2 f = __ldg(&feat[ei32[k]]);
                red_add_v2(&g_agg[dst[k]], f.x, f.y);
            }
        }
    } else {
        if (e + 3 < E) {
            int4 p0 = __ldcs(reinterpret_cast<const int4*>(g_edge) + 2 * i);
            int4 p1 = __ldcs(reinterpret_cast<const int4*>(g_edge) + 2 * i + 1);
            float2 f0 = __ldg(&feat[p0.x]);
            float2 f1 = __ldg(&feat[p0.z]);
            float2 f2 = __ldg(&feat[p1.x]);
            float2 f3 = __ldg(&feat[p1.z]);
            red_add_v2(&g_agg[p0.y], f0.x, f0.y);
            red_add_v2(&g_agg[p0.w], f1.x, f1.y);
            red_add_v2(&g_agg[p1.y], f2.x, f2.y);
            red_add_v2(&g_agg[p1.w], f3.x, f3.y);
        } else {
            for (long long k = e; k < E; k++) {
                int2 sd = g_edge[k];
                float2 f = __ldg(&feat[sd.x]);
                red_add_v2(&g_agg[sd.y], f.x, f.y);
            }
        }
    }
}

// Layer-1 epilogue + layer-2 down-projection + re-seed for second scatter.
__global__ void k_node_mid(const float* __restrict__ W1,
                           const float* __restrict__ b1,
                           const float* __restrict__ W2, int n) {
    int v = blockIdx.x * blockDim.x + threadIdx.x;
    if (v < n) {
        float dv = g_dinv[v];
        float2 g = g_agg[v];
        float ax = g.x * dv, ay = g.y * dv;   // finished layer-1 aggregation
        float t0 = 0.f, t1 = 0.f;
        #pragma unroll
        for (int j = 0; j < 16; j++) {
            float h = fmaf(ax, __ldg(&W1[j]),
                      fmaf(ay, __ldg(&W1[16 + j]), __ldg(&b1[j])));
            h = fmaxf(h, 0.f);
            t0 = fmaf(h, __ldg(&W2[2 * j]), t0);
            t1 = fmaf(h, __ldg(&W2[2 * j + 1]), t1);
        }
        float2 ts = make_float2(t0 * dv, t1 * dv);  // pre-scaled feature
        g_t[v] = ts;
        g_agg[v] = ts;                               // self-loop seed
    }
}

__global__ void k_out(const float* __restrict__ b2, float2* __restrict__ out, int n) {
    int v = blockIdx.x * blockDim.x + threadIdx.x;
    if (v < n) {
        float dv = g_dinv[v];
        float2 a = g_agg[v];
        float v0 = fmaf(a.x, dv, __ldg(&b2[0]));
        float v1 = fmaf(a.y, dv, __ldg(&b2[1]));
        float m = fmaxf(v0, v1);
        float lse = m + logf(expf(v0 - m) + expf(v1 - m));
        __stcs(&out[v], make_float2(v0 - lse, v1 - lse));
    }
}

extern "C" void kernel_launch(void* const* d_in, const int* in_sizes, int n_in,
                              void* d_out, int out_size) {
    const float2* x  = (const float2*)d_in[0];
    const void*   ei = d_in[1];                   // edge_index [2,E] (int32/int64)
    const float*  W1 = (const float*)d_in[2];     // [2,16]
    const float*  b1 = (const float*)d_in[3];     // [16]
    const float*  W2 = (const float*)d_in[4];     // [16,2]
    const float*  b2 = (const float*)d_in[5];     // [2]

    int       n = in_sizes[0] / 2;
    long long E = (long long)in_sizes[1] / 2;

    const int TPB = 256;
    int nb_n = (n + TPB - 1) / TPB;
    long long quarter = (E + 3) / 4;
    int nb_e = (int)((quarter + TPB - 1) / TPB);

    k_deg         <<<nb_e, TPB>>>(ei, E);
    k_node1       <<<nb_n, TPB>>>(x, n);
    k_edge<false> <<<nb_e, TPB>>>((const int*)ei, E);
    k_node_mid    <<<nb_n, TPB>>>(W1, b1, W2, n);
    k_edge<true>  <<<nb_e, TPB>>>((const int*)ei, E);
    k_out         <<<nb_n, TPB>>>(b2, (float2*)d_out, n);
}